// round 10
// baseline (speedup 1.0000x reference)
#include <cuda_runtime.h>
#include <cuda_fp16.h>
#include <cstdint>

#define MAXN 100000
#define CAP  96          // bucket capacity; P(Poisson(32) >= 96) ~ 1e-18 per node

// ---- device scratch (no allocations allowed) ----
__device__ int   g_cnt[MAXN];                        // per-node edge counts (cursor)
__device__ uint2 g_csr[(size_t)MAXN * CAP];          // padded buckets: (row, w-bits)
__device__ float g_dinv[MAXN];
__device__ __align__(128) float4 g_xp[MAXN];                 // xs = dinv*x (w=0)
__device__ __align__(128) __half g_h1[(size_t)MAXN * 32];    // hs1 = dinv*relu(...) fp16
__device__ __align__(128) __half g_agg[(size_t)MAXN * 32];   // dinv*agg1, fp16

// K1: zero counters
__global__ void k_zero(int n) {
    int i = blockIdx.x * blockDim.x + threadIdx.x;
    if (i < n) g_cnt[i] = 0;
}

// K2: scatter edges into per-target buckets (order within bucket irrelevant)
__global__ void k_scatter(const int* __restrict__ idx, const float* __restrict__ w, int E) {
    int e = blockIdx.x * blockDim.x + threadIdx.x;
    if (e >= E) return;
    int row = idx[e];
    int col = idx[E + e];
    int p = atomicAdd(&g_cnt[col], 1);
    if (p < CAP) g_csr[(size_t)col * CAP + p] = make_uint2((unsigned)row, __float_as_uint(w[e]));
}

// K3: warp/node: deg = 1 + sum(w) over bucket (coalesced); dinv; xs = dinv*x
__global__ void k_degdinv(const float* __restrict__ x, int n) {
    int wid  = (blockIdx.x * blockDim.x + threadIdx.x) >> 5;
    int lane = threadIdx.x & 31;
    if (wid >= n) return;
    int cnt = min(g_cnt[wid], CAP);
    const uint2* base = g_csr + (size_t)wid * CAP;
    float sum = 0.f;
    for (int e = lane; e < cnt; e += 32) sum += __uint_as_float(base[e].y);
#pragma unroll
    for (int o = 16; o; o >>= 1) sum += __shfl_xor_sync(0xffffffffu, sum, o);
    float dv = rsqrtf(1.0f + sum);
    if (lane == 0) {
        g_dinv[wid] = dv;
        g_xp[wid] = make_float4(x[3*wid] * dv, x[3*wid+1] * dv, x[3*wid+2] * dv, 0.f);
    }
}

// K4: layer-0 pull + fused W0 matmul/relu. Warp per node, lane per edge-slot.
// agg0 = xs[i] + sum w*xs[row]; h1 = dinv*relu(dinv*agg0 @ W0 + b0) (fp16 out).
__global__ void k_pull0(const float* __restrict__ W0, const float* __restrict__ b0, int n) {
    int wid  = (blockIdx.x * blockDim.x + threadIdx.x) >> 5;
    int lane = threadIdx.x & 31;
    if (wid >= n) return;
    int cnt = min(g_cnt[wid], CAP);
    const uint2* base = g_csr + (size_t)wid * CAP;
    float a0 = 0.f, a1 = 0.f, a2 = 0.f;
    for (int e = lane; e < cnt; e += 32) {
        uint2 c = base[e];
        float ww = __uint_as_float(c.y);
        float4 v = g_xp[c.x];
        a0 = fmaf(ww, v.x, a0); a1 = fmaf(ww, v.y, a1); a2 = fmaf(ww, v.z, a2);
    }
#pragma unroll
    for (int o = 16; o; o >>= 1) {
        a0 += __shfl_xor_sync(0xffffffffu, a0, o);
        a1 += __shfl_xor_sync(0xffffffffu, a1, o);
        a2 += __shfl_xor_sync(0xffffffffu, a2, o);
    }
    float4 xs = g_xp[wid];           // broadcast load (all lanes same addr)
    float dv = g_dinv[wid];
    a0 = (a0 + xs.x) * dv; a1 = (a1 + xs.y) * dv; a2 = (a2 + xs.z) * dv;
    // lane f computes output feature f
    float h = fmaf(a0, W0[lane], fmaf(a1, W0[32 + lane], fmaf(a2, W0[64 + lane], b0[lane])));
    h = fmaxf(h, 0.f) * dv;
    g_h1[(size_t)wid * 32 + lane] = __float2half(h);
}

// K5: layer-1 pull. Warp per node: 8 edge-slots x 4 chunks (16B each).
// fp32 register accumulation, write fp16 row once (dinv applied).
__global__ void k_pull1(int n) {
    int wid  = (blockIdx.x * blockDim.x + threadIdx.x) >> 5;
    int lane = threadIdx.x & 31;
    if (wid >= n) return;
    int esub  = lane >> 2;     // 0..7
    int chunk = lane & 3;      // 0..3
    int cnt = min(g_cnt[wid], CAP);
    const uint2* base = g_csr + (size_t)wid * CAP;
    const uint4* h1v = (const uint4*)g_h1;
    float acc[8] = {0.f,0.f,0.f,0.f,0.f,0.f,0.f,0.f};
    for (int e0 = 0; e0 < cnt; e0 += 8) {
        int e = e0 + esub;
        if (e < cnt) {
            uint2 c = base[e];
            float ww = __uint_as_float(c.y);
            uint4 p = h1v[(size_t)c.x * 4 + chunk];
            float2 f0 = __half22float2(*(half2*)&p.x);
            float2 f1 = __half22float2(*(half2*)&p.y);
            float2 f2 = __half22float2(*(half2*)&p.z);
            float2 f3 = __half22float2(*(half2*)&p.w);
            acc[0] = fmaf(ww, f0.x, acc[0]); acc[1] = fmaf(ww, f0.y, acc[1]);
            acc[2] = fmaf(ww, f1.x, acc[2]); acc[3] = fmaf(ww, f1.y, acc[3]);
            acc[4] = fmaf(ww, f2.x, acc[4]); acc[5] = fmaf(ww, f2.y, acc[5]);
            acc[6] = fmaf(ww, f3.x, acc[6]); acc[7] = fmaf(ww, f3.y, acc[7]);
        }
    }
    // reduce across esub (strides 4,8,16); chunk stays invariant
#pragma unroll
    for (int k = 0; k < 8; k++) {
        acc[k] += __shfl_xor_sync(0xffffffffu, acc[k], 4);
        acc[k] += __shfl_xor_sync(0xffffffffu, acc[k], 8);
        acc[k] += __shfl_xor_sync(0xffffffffu, acc[k], 16);
    }
    if (lane < 4) {   // lanes 0..3: chunk == lane
        uint4 sp = h1v[(size_t)wid * 4 + lane];   // self-loop term (w=1)
        float2 s0 = __half22float2(*(half2*)&sp.x);
        float2 s1 = __half22float2(*(half2*)&sp.y);
        float2 s2 = __half22float2(*(half2*)&sp.z);
        float2 s3 = __half22float2(*(half2*)&sp.w);
        float dv = g_dinv[wid];
        acc[0] = (acc[0] + s0.x) * dv; acc[1] = (acc[1] + s0.y) * dv;
        acc[2] = (acc[2] + s1.x) * dv; acc[3] = (acc[3] + s1.y) * dv;
        acc[4] = (acc[4] + s2.x) * dv; acc[5] = (acc[5] + s2.y) * dv;
        acc[6] = (acc[6] + s3.x) * dv; acc[7] = (acc[7] + s3.y) * dv;
        half2 p0 = __floats2half2_rn(acc[0], acc[1]);
        half2 p1 = __floats2half2_rn(acc[2], acc[3]);
        half2 p2 = __floats2half2_rn(acc[4], acc[5]);
        half2 p3 = __floats2half2_rn(acc[6], acc[7]);
        uint4 st;
        st.x = *(unsigned int*)&p0; st.y = *(unsigned int*)&p1;
        st.z = *(unsigned int*)&p2; st.w = *(unsigned int*)&p3;
        ((uint4*)g_agg)[(size_t)wid * 4 + lane] = st;
    }
}

// K6: per-graph block: h2 = relu(agg1 @ W1 + b1) (dinv already applied),
// mean-pool over sorted-batch range (binary search), head dot with Wr.
__global__ void k_pool(const int* __restrict__ batch,
                       const float* __restrict__ W1, const float* __restrict__ b1,
                       const float* __restrict__ Wr, const float* __restrict__ br,
                       float* __restrict__ out, int n) {
    int g = blockIdx.x;
    __shared__ float sW1[32 * 32];
    __shared__ float sb1[32];
    __shared__ float sWr[32];
    __shared__ int   sse[2];
    __shared__ float stile[8][33];
    __shared__ float spool[8][32];
    int tid = threadIdx.x;  // 256 threads
    for (int k = tid; k < 1024; k += 256) sW1[k] = W1[k];
    if (tid < 32) { sb1[tid] = b1[tid]; sWr[tid] = Wr[tid]; }
    if (tid < 2) {
        int key = g + tid;
        int lo = 0, hi = n;
        while (lo < hi) { int mid = (lo + hi) >> 1; if (batch[mid] < key) lo = mid + 1; else hi = mid; }
        sse[tid] = lo;
    }
    __syncthreads();
    int start = sse[0], end = sse[1];
    int feat = tid & 31, slot = tid >> 5;
    float acc = 0.f;
    for (int base = start; base < end; base += 8) {
        int nload = min(8, end - base);
        __syncthreads();
        if (slot < nload) {
            int node = base + slot;
            stile[slot][feat] = __half2float(g_agg[(size_t)node * 32 + feat]);
        }
        __syncthreads();
        if (slot < nload) {
            float v = sb1[feat];
#pragma unroll
            for (int jj = 0; jj < 32; jj++) v = fmaf(stile[slot][jj], sW1[jj * 32 + feat], v);
            acc += fmaxf(v, 0.f);
        }
    }
    spool[slot][feat] = acc;
    __syncthreads();
    if (tid < 32) {
        float s = 0.f;
#pragma unroll
        for (int k = 0; k < 8; k++) s += spool[k][tid];
        float cnt = (float)(end - start);
        float hg = s / fmaxf(cnt, 1.f);
        float p = hg * sWr[tid];
#pragma unroll
        for (int off = 16; off; off >>= 1) p += __shfl_down_sync(0xffffffffu, p, off);
        if (tid == 0) out[g] = p + br[0];
    }
}

extern "C" void kernel_launch(void* const* d_in, const int* in_sizes, int n_in,
                              void* d_out, int out_size) {
    const float* x     = (const float*)d_in[0];
    const int*   ei    = (const int*)d_in[1];
    const float* ew    = (const float*)d_in[2];
    const int*   batch = (const int*)d_in[3];
    const float* W0    = (const float*)d_in[4];
    const float* b0    = (const float*)d_in[5];
    const float* W1    = (const float*)d_in[6];
    const float* b1    = (const float*)d_in[7];
    const float* Wr    = (const float*)d_in[8];
    const float* br    = (const float*)d_in[9];
    float* out = (float*)d_out;

    int n = in_sizes[0] / 3;
    int E = in_sizes[2];
    int G = out_size;
    const int TB = 256;
    int warpGrid = (int)(((long long)n * 32 + TB - 1) / TB);

    k_zero   <<<(n + TB - 1) / TB, TB>>>(n);
    k_scatter<<<(E + TB - 1) / TB, TB>>>(ei, ew, E);
    k_degdinv<<<warpGrid, TB>>>(x, n);
    k_pull0  <<<warpGrid, TB>>>(W0, b0, n);
    k_pull1  <<<warpGrid, TB>>>(n);
    k_pool   <<<G, 256>>>(batch, W1, b1, Wr, br, out, n);
}

// round 11
// speedup vs baseline: 1.1496x; 1.1496x over previous
#include <cuda_runtime.h>
#include <cuda_fp16.h>
#include <cstdint>

#define MAXN 100000

// ---- device scratch (no allocations allowed) ----
__device__ float g_deg [MAXN];
__device__ float g_dinv[MAXN];
__device__ __align__(128) float4 g_xp  [MAXN];      // xs = dinv*x, padded (w=0)
__device__ __align__(128) float4 g_aggx[MAXN];      // layer-0 agg of xs (fp32)
__device__ __align__(128) float4 g_av  [MAXN];      // (a0,a1,a2,dinv): rank-3 h1 code
__device__ __align__(128) uint2  g_aggh[MAXN * 8];  // layer-1 agg fp16 [N x 32]

__device__ __forceinline__ void red_add_v4f(float4* addr, float4 v) {
    atomicAdd(addr, v);   // native fp32 vector red (cc >= 9.0)
}
__device__ __forceinline__ void red_add_v4h(void* addr, unsigned int a, unsigned int b,
                                            unsigned int c, unsigned int d) {
    asm volatile("red.global.add.noftz.v4.f16x2 [%0], {%1,%2,%3,%4};"
                 :: "l"(__cvta_generic_to_global(addr)),
                    "r"(a), "r"(b), "r"(c), "r"(d) : "memory");
}

// K1: deg starts at 1.0 (self-loop weight)
__global__ void k_init(int n) {
    int i = blockIdx.x * blockDim.x + threadIdx.x;
    if (i < n) g_deg[i] = 1.0f;
}

// K2: deg[col] += w over all edges
__global__ void k_deg(const int* __restrict__ idx, const float* __restrict__ w, int E) {
    int e = blockIdx.x * blockDim.x + threadIdx.x;
    if (e >= E) return;
    atomicAdd(&g_deg[idx[E + e]], w[e]);
}

// K3: dinv = rsqrt(deg); xs = dinv*x; seed layer-0 agg with self term xs
__global__ void k_dinv(const float* __restrict__ x, int n) {
    int i = blockIdx.x * blockDim.x + threadIdx.x;
    if (i >= n) return;
    float d  = g_deg[i];
    float dv = d > 0.f ? rsqrtf(d) : 0.f;
    g_dinv[i] = dv;
    float4 xs = make_float4(x[3*i] * dv, x[3*i+1] * dv, x[3*i+2] * dv, 0.f);
    g_xp[i]   = xs;
    g_aggx[i] = xs;
}

// K4: layer-0 edge pass (factorized norm), fp32 red.v4
__global__ void k_edge0(const int* __restrict__ idx, const float* __restrict__ w, int E) {
    int e = blockIdx.x * blockDim.x + threadIdx.x;
    if (e >= E) return;
    int row = idx[e];
    int col = idx[E + e];
    float ww = w[e];
    float4 v = g_xp[row];
    red_add_v4f(&g_aggx[col], make_float4(v.x * ww, v.y * ww, v.z * ww, 0.f));
}

// K5: per node: a = dinv*agg0; store (a,dinv); seed layer-1 agg with self
// h1 = dinv*relu(a@W0 + b0) in fp16. Thread per node (light compute).
__global__ void k_node0(const float* __restrict__ W0, const float* __restrict__ b0, int n) {
    int i = blockIdx.x * blockDim.x + threadIdx.x;
    if (i >= n) return;
    float4 ag = g_aggx[i];
    float dv  = g_dinv[i];
    float a0 = ag.x * dv, a1 = ag.y * dv, a2 = ag.z * dv;
    g_av[i] = make_float4(a0, a1, a2, dv);
    uint2* dst = g_aggh + i * 8;
#pragma unroll
    for (int j = 0; j < 8; j++) {
        float f[4];
#pragma unroll
        for (int k = 0; k < 4; k++) {
            int c = 4 * j + k;
            float h = fmaf(a0, W0[c], fmaf(a1, W0[32 + c], fmaf(a2, W0[64 + c], b0[c])));
            f[k] = fmaxf(h, 0.f) * dv;
        }
        half2 lo = __floats2half2_rn(f[0], f[1]);
        half2 hi = __floats2half2_rn(f[2], f[3]);
        uint2 p;
        p.x = *(unsigned int*)&lo;
        p.y = *(unsigned int*)&hi;
        dst[j] = p;
    }
}

// K6: layer-1 edge pass, rank-3 recompute. Quad of 4 lanes owns a strip of
// NE edges; lane j owns features [8j, 8j+8). Per edge: one 16B broadcast
// gather of (a,dinv), 24 FMA recompute, one red.v4.f16x2 (16B).
#define NE 8
__global__ void k_edge1(const int* __restrict__ idx, const float* __restrict__ w,
                        const float* __restrict__ W0, const float* __restrict__ b0, int E) {
    int t  = blockIdx.x * blockDim.x + threadIdx.x;
    int qd = t >> 2;          // quad id
    int j  = t & 3;           // lane-in-quad: features [8j, 8j+8)
    int e0 = qd * NE;
    if (e0 >= E) return;
    // preload W0 slice for this lane's 8 features (L1-broadcast, amortized)
    float w0r[8], w1r[8], w2r[8], b0r[8];
#pragma unroll
    for (int k = 0; k < 8; k++) {
        int c = 8 * j + k;
        w0r[k] = W0[c]; w1r[k] = W0[32 + c]; w2r[k] = W0[64 + c]; b0r[k] = b0[c];
    }
    int eend = min(e0 + NE, E);
    for (int e = e0; e < eend; e++) {
        int row = idx[e];
        int col = idx[E + e];
        float ww = w[e];
        float4 av = __ldg(g_av + row);          // 16B, quad-broadcast (1 sector)
        float s = av.w * ww;                    // dinv_row * w_e
        float f[8];
#pragma unroll
        for (int k = 0; k < 8; k++) {
            float h = fmaf(av.x, w0r[k], fmaf(av.y, w1r[k], fmaf(av.z, w2r[k], b0r[k])));
            f[k] = fmaxf(h, 0.f) * s;
        }
        half2 p0 = __floats2half2_rn(f[0], f[1]);
        half2 p1 = __floats2half2_rn(f[2], f[3]);
        half2 p2 = __floats2half2_rn(f[4], f[5]);
        half2 p3 = __floats2half2_rn(f[6], f[7]);
        red_add_v4h(&((uint4*)g_aggh)[col * 4 + j],
                    *(unsigned int*)&p0, *(unsigned int*)&p1,
                    *(unsigned int*)&p2, *(unsigned int*)&p3);
    }
}

// K7: per-graph block: h2 = relu(dinv*agg1 @ W1 + b1), mean-pool over
// sorted-batch range (binary search), head dot with Wr.
__global__ void k_pool(const int* __restrict__ batch,
                       const float* __restrict__ W1, const float* __restrict__ b1,
                       const float* __restrict__ Wr, const float* __restrict__ br,
                       float* __restrict__ out, int n) {
    int g = blockIdx.x;
    __shared__ float sW1[32 * 32];
    __shared__ float sb1[32];
    __shared__ float sWr[32];
    __shared__ int   sse[2];
    __shared__ float stile[8][33];
    __shared__ float spool[8][32];
    int tid = threadIdx.x;  // 256 threads
    for (int k = tid; k < 1024; k += 256) sW1[k] = W1[k];
    if (tid < 32) { sb1[tid] = b1[tid]; sWr[tid] = Wr[tid]; }
    if (tid < 2) {
        int key = g + tid;
        int lo = 0, hi = n;
        while (lo < hi) { int mid = (lo + hi) >> 1; if (batch[mid] < key) lo = mid + 1; else hi = mid; }
        sse[tid] = lo;
    }
    __syncthreads();
    int start = sse[0], end = sse[1];
    int feat = tid & 31, slot = tid >> 5;
    const __half* agg = (const __half*)g_aggh;
    float acc = 0.f;
    for (int base = start; base < end; base += 8) {
        int nload = min(8, end - base);
        __syncthreads();
        if (slot < nload) {
            int node = base + slot;
            stile[slot][feat] = g_dinv[node] * __half2float(agg[node * 32 + feat]);
        }
        __syncthreads();
        if (slot < nload) {
            float v = sb1[feat];
#pragma unroll
            for (int jj = 0; jj < 32; jj++) v = fmaf(stile[slot][jj], sW1[jj * 32 + feat], v);
            acc += fmaxf(v, 0.f);
        }
    }
    spool[slot][feat] = acc;
    __syncthreads();
    if (tid < 32) {
        float s = 0.f;
#pragma unroll
        for (int k = 0; k < 8; k++) s += spool[k][tid];
        float cnt = (float)(end - start);
        float hg = s / fmaxf(cnt, 1.f);
        float p = hg * sWr[tid];
#pragma unroll
        for (int off = 16; off; off >>= 1) p += __shfl_down_sync(0xffffffffu, p, off);
        if (tid == 0) out[g] = p + br[0];
    }
}

extern "C" void kernel_launch(void* const* d_in, const int* in_sizes, int n_in,
                              void* d_out, int out_size) {
    const float* x     = (const float*)d_in[0];
    const int*   ei    = (const int*)d_in[1];
    const float* ew    = (const float*)d_in[2];
    const int*   batch = (const int*)d_in[3];
    const float* W0    = (const float*)d_in[4];
    const float* b0    = (const float*)d_in[5];
    const float* W1    = (const float*)d_in[6];
    const float* b1    = (const float*)d_in[7];
    const float* Wr    = (const float*)d_in[8];
    const float* br    = (const float*)d_in[9];
    float* out = (float*)d_out;

    int n = in_sizes[0] / 3;
    int E = in_sizes[2];
    int G = out_size;
    const int TB = 256;

    k_init <<<(n + TB - 1) / TB, TB>>>(n);
    k_deg  <<<(E + TB - 1) / TB, TB>>>(ei, ew, E);
    k_dinv <<<(n + TB - 1) / TB, TB>>>(x, n);
    k_edge0<<<(E + TB - 1) / TB, TB>>>(ei, ew, E);
    k_node0<<<(n + TB - 1) / TB, TB>>>(W0, b0, n);
    long long quads = ((long long)E + NE - 1) / NE;
    long long t1 = quads * 4;
    k_edge1<<<(int)((t1 + TB - 1) / TB), TB>>>(ei, ew, W0, b0, E);
    k_pool <<<G, 256>>>(batch, W1, b1, Wr, br, out, n);
}